// round 5
// baseline (speedup 1.0000x reference)
#include <cuda_runtime.h>
#include <cuda_fp16.h>
#include <math.h>
#include <stdint.h>

// ---------------------------------------------------------------------------
// Problem constants
// ---------------------------------------------------------------------------
namespace {
constexpr int Bb   = 2;
constexpr int Hh   = 512;
constexpr int Ww   = 512;
constexpr int Np   = Hh * Ww;
constexpr int Cc   = 48;
constexpr int C3   = 144;
constexpr int HID  = 127;
constexpr int NPART  = 1024;
constexpr int CHUNK  = Np / NPART;
constexpr int GSLOTS = 48 * 48 + 96;
constexpr int PXD = 392;   // halo pixel stride (halves), 390 used
}

// ---------------------------------------------------------------------------
// Scratch
// ---------------------------------------------------------------------------
__device__ float  g_patch[(size_t)Bb * Cc * Np];
__device__ __half g_qkv0 [(size_t)Bb * C3 * Np];
__device__ __half g_qk   [(size_t)Bb * 96 * Np];   // dw'd q,k only
__device__ float  g_first[(size_t)Bb * Cc * Np];
__device__ __half g_gate [(size_t)Bb * HID * Np];
__device__ float  g_part [(size_t)Bb * NPART * GSLOTS];
__device__ float  g_gfin [Bb * GSLOTS];
__device__ float  g_M    [Bb * 48 * 48];

// ---------------------------------------------------------------------------
// tf32 helpers
// ---------------------------------------------------------------------------
__device__ __forceinline__ uint32_t f2tf(float f) {
  uint32_t r;
  asm("cvt.rna.tf32.f32 %0, %1;" : "=r"(r) : "f"(f));
  return r;
}
__device__ __forceinline__ void mma_tf32(float c[4], uint32_t a0, uint32_t a1,
                                         uint32_t a2, uint32_t a3, uint32_t b0,
                                         uint32_t b1) {
  asm volatile(
      "mma.sync.aligned.m16n8k8.row.col.f32.tf32.tf32.f32 "
      "{%0,%1,%2,%3}, {%4,%5,%6,%7}, {%8,%9}, {%0,%1,%2,%3};"
      : "+f"(c[0]), "+f"(c[1]), "+f"(c[2]), "+f"(c[3])
      : "r"(a0), "r"(a1), "r"(a2), "r"(a3), "r"(b0), "r"(b1));
}
__device__ __forceinline__ float gelu_exact(float u) {
  return 0.5f * u * (1.f + erff(u * 0.70710678118654752f)) ;
}

// ---------------------------------------------------------------------------
// K1: patch embed conv 3x3, 3 -> 48 (fp32)
// ---------------------------------------------------------------------------
__global__ __launch_bounds__(128) void k_pe(const float* __restrict__ x,
                                            const float* __restrict__ pw,
                                            float* __restrict__ out) {
  __shared__ float ws[48 * 27];
  __shared__ float si[3][3][514];
  int b = blockIdx.x / Hh, y = blockIdx.x % Hh;
  int tid = threadIdx.x;
  for (int i = tid; i < 48 * 27; i += 128) ws[i] = pw[i];
  for (int i = tid; i < 3 * 3 * 512; i += 128) {
    int ch = i / 1536, r = (i / 512) % 3, xx = i % 512;
    int yy = y - 1 + r;
    float v = (yy >= 0 && yy < Hh)
                  ? x[((size_t)(b * 3 + ch) * Hh + yy) * Ww + xx]
                  : 0.f;
    si[ch][r][xx + 1] = v;
  }
  if (tid < 9) {
    int ch = tid / 3, r = tid % 3;
    si[ch][r][0] = 0.f;
    si[ch][r][513] = 0.f;
  }
  __syncthreads();

  int x0 = tid * 4;
  float rv[3][3][6];
#pragma unroll
  for (int ch = 0; ch < 3; ch++)
#pragma unroll
    for (int r = 0; r < 3; r++)
#pragma unroll
      for (int d = 0; d < 6; d++) rv[ch][r][d] = si[ch][r][x0 + d];

  float* op = out + (size_t)b * Cc * Np + (size_t)y * Ww + x0;
  for (int o = 0; o < 48; o++) {
    float a0 = 0.f, a1 = 0.f, a2 = 0.f, a3 = 0.f;
#pragma unroll
    for (int ch = 0; ch < 3; ch++)
#pragma unroll
      for (int r = 0; r < 3; r++)
#pragma unroll
        for (int dx = 0; dx < 3; dx++) {
          float w = ws[o * 27 + ch * 9 + r * 3 + dx];
          a0 = fmaf(rv[ch][r][dx + 0], w, a0);
          a1 = fmaf(rv[ch][r][dx + 1], w, a1);
          a2 = fmaf(rv[ch][r][dx + 2], w, a2);
          a3 = fmaf(rv[ch][r][dx + 3], w, a3);
        }
    *reinterpret_cast<float4*>(op + (size_t)o * Np) = make_float4(a0, a1, a2, a3);
  }
}

// ---------------------------------------------------------------------------
// Tensor-core pixel GEMM (round-4 proven): used for qkv (LN) and fo.
// ---------------------------------------------------------------------------
template <int K, int KC, int BN, bool LN, bool RES, typename TIN, typename TOUT>
__global__ __launch_bounds__((BN / 16) * 64) void k_tgemm(
    const TIN* __restrict__ in, int in_cs, int in_co,
    const float* __restrict__ w, const float* __restrict__ nw,
    const float* __restrict__ nb, const float* __restrict__ res, int res_cs,
    TOUT* __restrict__ out, int out_cs, int CO) {
  constexpr int MT = BN / 16;
  constexpr int NTH = MT * 64;
  constexpr int SBd = 132;
  constexpr int SAd = BN + 4;
  constexpr int KSTEPS = KC / 8;

  extern __shared__ float smf[];
  float* sB = smf;
  float* sA = smf + KC * SBd;
  float* tail = sA + KC * SAd;
  float* mu = tail;
  float* rs = tail + 128;
  float* snw = tail + 256;
  float* snb = tail + 304;

  int tid = threadIdx.x;
  int wid = tid / 32, lane = tid % 32;
  int warp_m = wid % MT, warp_n = wid / MT;
  int n0 = warp_n * 64;
  int o0 = blockIdx.x * BN;
  int pb = blockIdx.y;
  int b = pb / (Np / 128);
  int n0g = (pb % (Np / 128)) * 128;

  const TIN* ip = in + ((size_t)b * in_cs + in_co) * Np + n0g;
  const float* wp = w;

  float acc[8][4];
#pragma unroll
  for (int j = 0; j < 8; j++)
#pragma unroll
    for (int i = 0; i < 4; i++) acc[j][i] = 0.f;

  for (int k0 = 0; k0 < K; k0 += KC) {
    for (int i = tid; i < KC * BN; i += NTH) {
      int k = i / BN, m = i % BN;
      int o = o0 + m, kk = k0 + k;
      sA[k * SAd + m] = (o < CO && kk < K) ? wp[(size_t)o * K + kk] : 0.f;
    }
    if constexpr (LN) {
      for (int i = tid; i < KC * 128; i += NTH) {
        int k = i >> 7, j = i & 127;
        sB[k * SBd + j] = (float)ip[(size_t)k * Np + j];
      }
      for (int i = tid; i < K; i += NTH) {
        snw[i] = nw[i];
        snb[i] = nb[i];
      }
      __syncthreads();
      for (int j = tid; j < 128; j += NTH) {
        float s = 0.f;
#pragma unroll 8
        for (int k = 0; k < K; k++) s += sB[k * SBd + j];
        float m = s * (1.f / (float)K);
        float v = 0.f;
#pragma unroll 8
        for (int k = 0; k < K; k++) {
          float d = sB[k * SBd + j] - m;
          v = fmaf(d, d, v);
        }
        mu[j] = m;
        rs[j] = rsqrtf(v * (1.f / (float)K) + 1e-5f);
      }
      __syncthreads();
      for (int i = tid; i < KC * 128; i += NTH) {
        int k = i >> 7, j = i & 127;
        sB[k * SBd + j] = (sB[k * SBd + j] - mu[j]) * rs[j] * snw[k] + snb[k];
      }
    } else if constexpr (sizeof(TIN) == 2) {
      for (int i = tid; i < KC * 64; i += NTH) {
        int k = i >> 6, j2 = i & 63;
        int kk = k0 + k;
        float2 f = make_float2(0.f, 0.f);
        if (kk < K) {
          __half2 h =
              *reinterpret_cast<const __half2*>(ip + (size_t)kk * Np + 2 * j2);
          f = __half22float2(h);
        }
        sB[k * SBd + 2 * j2] = f.x;
        sB[k * SBd + 2 * j2 + 1] = f.y;
      }
    } else {
      for (int i = tid; i < KC * 128; i += NTH) {
        int k = i >> 7, j = i & 127;
        int kk = k0 + k;
        sB[k * SBd + j] = (kk < K) ? (float)ip[(size_t)kk * Np + j] : 0.f;
      }
    }
    __syncthreads();

    int tg = lane & 3, gr = lane >> 2;
#pragma unroll
    for (int ks = 0; ks < KSTEPS; ks++) {
      int kr0 = ks * 8 + tg;
      float a0f = sA[kr0 * SAd + warp_m * 16 + gr];
      float a1f = sA[kr0 * SAd + warp_m * 16 + gr + 8];
      float a2f = sA[(kr0 + 4) * SAd + warp_m * 16 + gr];
      float a3f = sA[(kr0 + 4) * SAd + warp_m * 16 + gr + 8];
      uint32_t ah0 = f2tf(a0f), ah1 = f2tf(a1f), ah2 = f2tf(a2f),
               ah3 = f2tf(a3f);
      uint32_t al0 = f2tf(a0f - __uint_as_float(ah0));
      uint32_t al1 = f2tf(a1f - __uint_as_float(ah1));
      uint32_t al2 = f2tf(a2f - __uint_as_float(ah2));
      uint32_t al3 = f2tf(a3f - __uint_as_float(ah3));
#pragma unroll
      for (int j = 0; j < 8; j++) {
        float b0f = sB[kr0 * SBd + n0 + j * 8 + gr];
        float b1f = sB[(kr0 + 4) * SBd + n0 + j * 8 + gr];
        uint32_t bh0 = f2tf(b0f), bh1 = f2tf(b1f);
        mma_tf32(acc[j], ah0, ah1, ah2, ah3, bh0, bh1);
        mma_tf32(acc[j], al0, al1, al2, al3, bh0, bh1);
      }
    }
    if (k0 + KC < K) __syncthreads();
  }

  int gr = lane >> 2, tg = lane & 3;
#pragma unroll
  for (int j = 0; j < 8; j++) {
    int nn = n0 + j * 8 + 2 * tg;
#pragma unroll
    for (int h = 0; h < 2; h++) {
      int o = o0 + warp_m * 16 + gr + h * 8;
      if (o < CO) {
        float2 r = make_float2(acc[j][h * 2], acc[j][h * 2 + 1]);
        if constexpr (RES) {
          const float2 q = *reinterpret_cast<const float2*>(
              res + ((size_t)b * res_cs + o) * Np + n0g + nn);
          r.x += q.x;
          r.y += q.y;
        }
        if constexpr (sizeof(TOUT) == 2) {
          *reinterpret_cast<__half2*>(out + ((size_t)b * out_cs + o) * Np +
                                      n0g + nn) = __floats2half2_rn(r.x, r.y);
        } else {
          *reinterpret_cast<float2*>(out + ((size_t)b * out_cs + o) * Np +
                                     n0g + nn) = r;
        }
      }
    }
  }
}

// ---------------------------------------------------------------------------
// Depthwise 3x3 on q,k channels only (96), fp16 in/out.
// ---------------------------------------------------------------------------
__global__ __launch_bounds__(256) void k_dw96(const __half* __restrict__ in,
                                              const float* __restrict__ w9,
                                              __half* __restrict__ out) {
  int idx = blockIdx.x * 256 + threadIdx.x;
  int total = Bb * 96 * Hh * (Ww / 8);
  if (idx >= total) return;
  int xq = idx % (Ww / 8);
  int t = idx / (Ww / 8);
  int y = t % Hh; t /= Hh;
  int c = t % 96;
  int b = t / 96;
  int x0 = xq * 8;

  float wv[9];
#pragma unroll
  for (int i = 0; i < 9; i++) wv[i] = w9[c * 9 + i];

  const __half* base = in + ((size_t)b * C3 + c) * Np;
  float a[8];
#pragma unroll
  for (int p = 0; p < 8; p++) a[p] = 0.f;

#pragma unroll
  for (int dy = 0; dy < 3; dy++) {
    int yy = y + dy - 1;
    if (yy < 0 || yy >= Hh) continue;
    const __half* row = base + (size_t)yy * Ww;
    float v[10];
    v[0] = (x0 > 0) ? __half2float(row[x0 - 1]) : 0.f;
    uint4 m = *reinterpret_cast<const uint4*>(row + x0);
    const __half2* hp = reinterpret_cast<const __half2*>(&m);
#pragma unroll
    for (int q = 0; q < 4; q++) {
      float2 f = __half22float2(hp[q]);
      v[1 + 2 * q] = f.x;
      v[2 + 2 * q] = f.y;
    }
    v[9] = (x0 + 8 < Ww) ? __half2float(row[x0 + 8]) : 0.f;
#pragma unroll
    for (int dx = 0; dx < 3; dx++) {
      float wt = wv[dy * 3 + dx];
#pragma unroll
      for (int p = 0; p < 8; p++) a[p] = fmaf(v[dx + p], wt, a[p]);
    }
  }
  __half2 o4[4];
#pragma unroll
  for (int q = 0; q < 4; q++) o4[q] = __floats2half2_rn(a[2 * q], a[2 * q + 1]);
  *reinterpret_cast<uint4*>(out + ((size_t)b * 96 + c) * Np + (size_t)y * Ww +
                            x0) = *reinterpret_cast<uint4*>(o4);
}

// ---------------------------------------------------------------------------
// Fused attn-v GEMM: first = patch + M @ dw(v).   dw applied in staging.
// 192 threads; per-128px tile; v staged raw from qkv0 (3x130 halo).
// ---------------------------------------------------------------------------
__global__ __launch_bounds__(192, 3) void k_av(
    const __half* __restrict__ qkv0, const float* __restrict__ patch,
    const float* __restrict__ Mmat, const float* __restrict__ dw_w,
    float* __restrict__ first) {
  extern __shared__ char smraw[];
  __half* sRaw = (__half*)smraw;                     // [48][PXD]
  float* sB = (float*)(sRaw + 48 * PXD);             // [48][132]
  float* sA = sB + 48 * 132;                         // [48][52]
  float* sDW = sA + 48 * 52;                         // [48][12]

  int tid = threadIdx.x;
  int wid = tid / 32, lane = tid % 32;
  int pb = blockIdx.x;
  int b = pb / (Np / 128);
  int t = pb % (Np / 128);
  int y = t / (Ww / 128);
  int x0 = (t % (Ww / 128)) * 128;

  for (int i = tid; i < 48 * 390; i += 192) {
    int c = i / 390, p = i % 390;
    int r = p / 130, q = p % 130;
    int yy = y + r - 1, xx = x0 + q - 1;
    bool valid = (yy >= 0 && yy < Hh && xx >= 0 && xx < Ww);
    sRaw[c * PXD + p] =
        valid ? qkv0[((size_t)b * C3 + 96 + c) * Np + (size_t)yy * Ww + xx]
              : __half(0.f);
  }
  for (int i = tid; i < 48 * 48; i += 192) {
    int c = i / 48, o = i % 48;
    sA[c * 52 + o] = Mmat[(size_t)b * 2304 + o * 48 + c];
  }
  for (int i = tid; i < 48 * 9; i += 192) {
    int c = i / 9, j = i % 9;
    sDW[c * 12 + j] = dw_w[(96 + c) * 9 + j];
  }
  __syncthreads();

  // depthwise into sB
  for (int task = tid; task < 48 * 32; task += 192) {
    int c = task >> 5;
    int j4 = (task & 31) * 4;
    float a[4] = {0.f, 0.f, 0.f, 0.f};
    const float* w = sDW + c * 12;
#pragma unroll
    for (int r = 0; r < 3; r++) {
      const __half* h = sRaw + c * PXD + r * 130 + j4;
      float v[6];
#pragma unroll
      for (int d = 0; d < 6; d++) v[d] = __half2float(h[d]);
#pragma unroll
      for (int dx = 0; dx < 3; dx++) {
        float wt = w[r * 3 + dx];
#pragma unroll
        for (int p = 0; p < 4; p++) a[p] = fmaf(v[dx + p], wt, a[p]);
      }
    }
#pragma unroll
    for (int p = 0; p < 4; p++) sB[c * 132 + j4 + p] = a[p];
  }
  __syncthreads();

  // mma: 3 m-tiles x 2 n-halves
  int warp_m = wid % 3, warp_n = wid / 3;
  int n0 = warp_n * 64;
  int tg = lane & 3, gr = lane >> 2;
  float acc[8][4];
#pragma unroll
  for (int j = 0; j < 8; j++)
#pragma unroll
    for (int i = 0; i < 4; i++) acc[j][i] = 0.f;

#pragma unroll
  for (int ks = 0; ks < 6; ks++) {
    int kr0 = ks * 8 + tg;
    float a0f = sA[kr0 * 52 + warp_m * 16 + gr];
    float a1f = sA[kr0 * 52 + warp_m * 16 + gr + 8];
    float a2f = sA[(kr0 + 4) * 52 + warp_m * 16 + gr];
    float a3f = sA[(kr0 + 4) * 52 + warp_m * 16 + gr + 8];
    uint32_t ah0 = f2tf(a0f), ah1 = f2tf(a1f), ah2 = f2tf(a2f), ah3 = f2tf(a3f);
    uint32_t al0 = f2tf(a0f - __uint_as_float(ah0));
    uint32_t al1 = f2tf(a1f - __uint_as_float(ah1));
    uint32_t al2 = f2tf(a2f - __uint_as_float(ah2));
    uint32_t al3 = f2tf(a3f - __uint_as_float(ah3));
#pragma unroll
    for (int j = 0; j < 8; j++) {
      float b0f = sB[kr0 * 132 + 130 + n0 + j * 8 + gr - 130];  // center row
      float b1f = sB[(kr0 + 4) * 132 + n0 + j * 8 + gr];
      // NOTE: sB holds dw output indexed by output pixel 0..127 directly
      b0f = sB[kr0 * 132 + n0 + j * 8 + gr];
      uint32_t bh0 = f2tf(b0f), bh1 = f2tf(b1f);
      mma_tf32(acc[j], ah0, ah1, ah2, ah3, bh0, bh1);
      mma_tf32(acc[j], al0, al1, al2, al3, bh0, bh1);
    }
  }

#pragma unroll
  for (int j = 0; j < 8; j++) {
    int nn = n0 + j * 8 + 2 * tg;
#pragma unroll
    for (int h = 0; h < 2; h++) {
      int o = warp_m * 16 + gr + h * 8;
      size_t base = ((size_t)b * 48 + o) * Np + (size_t)y * Ww + x0 + nn;
      float2 q = *reinterpret_cast<const float2*>(patch + base);
      float2 r = make_float2(acc[j][h * 2] + q.x, acc[j][h * 2 + 1] + q.y);
      *reinterpret_cast<float2*>(first + base) = r;
    }
  }
}

// ---------------------------------------------------------------------------
// Fused GDFN front: gate = gelu(dw(pi1(LN2(first)))) * dw(pi2(LN2(first)))
// 256 threads, per-128px tile, 8 chunks of 16 hidden pairs; h in smem fp16.
// ---------------------------------------------------------------------------
__global__ __launch_bounds__(256, 2) void k_pigate(
    const float* __restrict__ first, const float* __restrict__ nw,
    const float* __restrict__ nb, const float* __restrict__ pi_w,
    const float* __restrict__ dw_w, __half* __restrict__ gate) {
  extern __shared__ char smraw[];
  __half* sX = (__half*)smraw;                  // [48][PXD]
  __half* sH = sX + 48 * PXD;                   // [32][PXD]
  float* sPW = (float*)(sH + 32 * PXD);         // [48][36]
  float* sDW = sPW + 48 * 36;                   // [32][12]
  float* mu = sDW + 32 * 12;                    // [PXD]
  float* rs = mu + PXD;                         // [PXD]
  float* snw = rs + PXD;
  float* snb = snw + 48;

  int tid = threadIdx.x;
  int wid = tid / 32, lane = tid % 32;
  int tg = lane & 3, gr = lane >> 2;

  int pb = blockIdx.x;
  int b = pb / (Np / 128);
  int t = pb % (Np / 128);
  int y = t / (Ww / 128);
  int x0 = (t % (Ww / 128)) * 128;

  for (int i = tid; i < 48; i += 256) {
    snw[i] = nw[i];
    snb[i] = nb[i];
  }
  // pass 1: LN statistics straight from global (L2-resident on re-reads)
  for (int p = tid; p < 390; p += 256) {
    int r = p / 130, q = p % 130;
    int yy = y + r - 1, xx = x0 + q - 1;
    bool valid = (yy >= 0 && yy < Hh && xx >= 0 && xx < Ww);
    float m = 0.f, v = 0.f;
    if (valid) {
      const float* fp = first + (size_t)b * 48 * Np + (size_t)yy * Ww + xx;
      float s = 0.f;
#pragma unroll 8
      for (int k = 0; k < 48; k++) s += fp[(size_t)k * Np];
      m = s * (1.f / 48.f);
#pragma unroll 8
      for (int k = 0; k < 48; k++) {
        float d = fp[(size_t)k * Np] - m;
        v = fmaf(d, d, v);
      }
      v = rsqrtf(v * (1.f / 48.f) + 1e-5f);
    } else {
      v = -1.f;
    }
    mu[p] = m;
    rs[p] = v;
  }
  __syncthreads();
  // pass 2: normalize -> sX fp16
  for (int i = tid; i < 48 * PXD; i += 256) {
    int c = i / PXD, p = i % PXD;
    float val = 0.f;
    if (p < 390) {
      float r_ = rs[p];
      if (r_ > 0.f) {
        int r = p / 130, q = p % 130;
        int yy = y + r - 1, xx = x0 + q - 1;
        float xv = first[((size_t)b * 48 + c) * Np + (size_t)yy * Ww + xx];
        val = (xv - mu[p]) * r_ * snw[c] + snb[c];
      }
    }
    sX[c * PXD + p] = __float2half(val);
  }

  int m0 = (wid & 1) * 16;       // pi-mma m tile
  int ngrp = wid >> 1;           // 0..3, each 104 px
  for (int ch = 0; ch < 8; ch++) {
    __syncthreads();
    // stage weights
    for (int i = tid; i < 48 * 32; i += 256) {
      int k = i / 32, m = i % 32;
      int hid = ch * 16 + (m & 15);
      float v = 0.f;
      if (hid < HID) {
        int row = (m < 16) ? hid : (HID + hid);
        v = pi_w[row * 48 + k];
      }
      sPW[k * 36 + m] = v;
    }
    for (int i = tid; i < 32 * 9; i += 256) {
      int m = i / 9, j = i % 9;
      int hid = ch * 16 + (m & 15);
      float v = 0.f;
      if (hid < HID) {
        int row = (m < 16) ? hid : (HID + hid);
        v = dw_w[row * 9 + j];
      }
      sDW[m * 12 + j] = v;
    }
    __syncthreads();

    // pi mma: h[32][390] (A fp32 hi/lo 2-pass, B fp16 -> tf32 exact)
    {
      float acc[13][4];
#pragma unroll
      for (int j = 0; j < 13; j++)
#pragma unroll
        for (int i = 0; i < 4; i++) acc[j][i] = 0.f;
#pragma unroll
      for (int ks = 0; ks < 6; ks++) {
        int kr0 = ks * 8 + tg;
        float a0f = sPW[kr0 * 36 + m0 + gr];
        float a1f = sPW[kr0 * 36 + m0 + gr + 8];
        float a2f = sPW[(kr0 + 4) * 36 + m0 + gr];
        float a3f = sPW[(kr0 + 4) * 36 + m0 + gr + 8];
        uint32_t ah0 = f2tf(a0f), ah1 = f2tf(a1f), ah2 = f2tf(a2f),
                 ah3 = f2tf(a3f);
        uint32_t al0 = f2tf(a0f - __uint_as_float(ah0));
        uint32_t al1 = f2tf(a1f - __uint_as_float(ah1));
        uint32_t al2 = f2tf(a2f - __uint_as_float(ah2));
        uint32_t al3 = f2tf(a3f - __uint_as_float(ah3));
#pragma unroll
        for (int j = 0; j < 13; j++) {
          int nn0 = ngrp * 104 + j * 8;
          if (nn0 <= PXD - 8) {
            float b0f = __half2float(sX[kr0 * PXD + nn0 + gr]);
            float b1f = __half2float(sX[(kr0 + 4) * PXD + nn0 + gr]);
            uint32_t bh0 = f2tf(b0f), bh1 = f2tf(b1f);
            mma_tf32(acc[j], ah0, ah1, ah2, ah3, bh0, bh1);
            mma_tf32(acc[j], al0, al1, al2, al3, bh0, bh1);
          }
        }
      }
#pragma unroll
      for (int j = 0; j < 13; j++) {
        int nn = ngrp * 104 + j * 8 + 2 * tg;
        if (nn <= PXD - 2) {
          *reinterpret_cast<__half2*>(sH + (m0 + gr) * PXD + nn) =
              __floats2half2_rn(acc[j][0], acc[j][1]);
          *reinterpret_cast<__half2*>(sH + (m0 + gr + 8) * PXD + nn) =
              __floats2half2_rn(acc[j][2], acc[j][3]);
        }
      }
    }
    __syncthreads();

    // dw + gelu gate -> global
    for (int task = tid; task < 16 * 32; task += 256) {
      int pp = task >> 5;
      int j4 = (task & 31) * 4;
      int hid = ch * 16 + pp;
      float a1[4] = {0.f, 0.f, 0.f, 0.f};
      float a2[4] = {0.f, 0.f, 0.f, 0.f};
      const float* w1 = sDW + pp * 12;
      const float* w2 = sDW + (pp + 16) * 12;
#pragma unroll
      for (int r = 0; r < 3; r++) {
        const __half* h1 = sH + pp * PXD + r * 130 + j4;
        const __half* h2 = sH + (pp + 16) * PXD + r * 130 + j4;
        float v1[6], v2[6];
#pragma unroll
        for (int d = 0; d < 6; d++) {
          v1[d] = __half2float(h1[d]);
          v2[d] = __half2float(h2[d]);
        }
#pragma unroll
        for (int dx = 0; dx < 3; dx++) {
          float wa = w1[r * 3 + dx], wb = w2[r * 3 + dx];
#pragma unroll
          for (int p = 0; p < 4; p++) {
            a1[p] = fmaf(v1[dx + p], wa, a1[p]);
            a2[p] = fmaf(v2[dx + p], wb, a2[p]);
          }
        }
      }
      if (hid < HID) {
        __half2 o0 = __floats2half2_rn(gelu_exact(a1[0]) * a2[0],
                                       gelu_exact(a1[1]) * a2[1]);
        __half2 o1 = __floats2half2_rn(gelu_exact(a1[2]) * a2[2],
                                       gelu_exact(a1[3]) * a2[3]);
        __half* gp = gate + ((size_t)b * HID + hid) * Np + (size_t)y * Ww +
                     x0 + j4;
        *reinterpret_cast<__half2*>(gp) = o0;
        *reinterpret_cast<__half2*>(gp + 2) = o1;
      }
    }
  }
}

// ---------------------------------------------------------------------------
// Gram partials (fp16, q/k buffer stride 96)
// ---------------------------------------------------------------------------
__global__ __launch_bounds__(96) void k_gram(const __half* __restrict__ qk,
                                             float* __restrict__ part) {
  __shared__ float sQ[48 * 33];
  __shared__ float sK[48 * 33];
  int blk = blockIdx.x;
  int b = blk / NPART, pc = blk % NPART;
  int n0 = pc * CHUNK;
  const __half* q = qk + (size_t)b * 96 * Np;
  const __half* k = q + (size_t)48 * Np;
  int tid = threadIdx.x;
  int ct = tid / 12, dt = tid % 12;
  int c0 = ct * 6, d0 = dt * 4;

  float acc[6][4];
#pragma unroll
  for (int i = 0; i < 6; i++)
#pragma unroll
    for (int j = 0; j < 4; j++) acc[i][j] = 0.f;
  float nacc = 0.f;

  for (int t = 0; t < CHUNK / 32; t++) {
    int off = n0 + t * 32;
    __syncthreads();
    for (int i = tid; i < 48 * 16; i += 96) {
      int c = i / 16, j2 = i % 16;
      float2 fq = __half22float2(
          *reinterpret_cast<const __half2*>(q + (size_t)c * Np + off + 2 * j2));
      float2 fk = __half22float2(
          *reinterpret_cast<const __half2*>(k + (size_t)c * Np + off + 2 * j2));
      sQ[c * 33 + 2 * j2] = fq.x;
      sQ[c * 33 + 2 * j2 + 1] = fq.y;
      sK[c * 33 + 2 * j2] = fk.x;
      sK[c * 33 + 2 * j2 + 1] = fk.y;
    }
    __syncthreads();
#pragma unroll 4
    for (int j = 0; j < 32; j++) {
      float qa[6], kb[4];
#pragma unroll
      for (int i = 0; i < 6; i++) qa[i] = sQ[(c0 + i) * 33 + j];
#pragma unroll
      for (int i = 0; i < 4; i++) kb[i] = sK[(d0 + i) * 33 + j];
#pragma unroll
      for (int i = 0; i < 6; i++)
#pragma unroll
        for (int jj = 0; jj < 4; jj++)
          acc[i][jj] = fmaf(qa[i], kb[jj], acc[i][jj]);
    }
    {
      const float* s = (tid < 48) ? (sQ + tid * 33) : (sK + (tid - 48) * 33);
#pragma unroll 8
      for (int j = 0; j < 32; j++) {
        float v = s[j];
        nacc = fmaf(v, v, nacc);
      }
    }
  }
  float* pp = part + (size_t)blk * GSLOTS;
#pragma unroll
  for (int i = 0; i < 6; i++)
#pragma unroll
    for (int jj = 0; jj < 4; jj++) pp[(c0 + i) * 48 + d0 + jj] = acc[i][jj];
  pp[2304 + tid] = nacc;
}

__global__ void k_red(const float* __restrict__ part, float* __restrict__ gfin) {
  int s = blockIdx.x * blockDim.x + threadIdx.x;
  if (s >= Bb * GSLOTS) return;
  int b = s / GSLOTS, slot = s % GSLOTS;
  const float* p = part + (size_t)b * NPART * GSLOTS + slot;
  float a0 = 0.f, a1 = 0.f, a2 = 0.f, a3 = 0.f;
  for (int i = 0; i < NPART; i += 4) {
    a0 += p[(size_t)(i + 0) * GSLOTS];
    a1 += p[(size_t)(i + 1) * GSLOTS];
    a2 += p[(size_t)(i + 2) * GSLOTS];
    a3 += p[(size_t)(i + 3) * GSLOTS];
  }
  gfin[s] = (a0 + a1) + (a2 + a3);
}

__global__ __launch_bounds__(256) void k_att(const float* __restrict__ gfin,
                                             const float* __restrict__ temp,
                                             const float* __restrict__ po,
                                             float* __restrict__ M) {
  __shared__ float sG[2304];
  __shared__ float sAt[2304];
  __shared__ float snq[48], snk[48];
  int b = blockIdx.x, tid = threadIdx.x;
  const float* g = gfin + (size_t)b * GSLOTS;
  for (int i = tid; i < 2304; i += 256) sG[i] = g[i];
  if (tid < 96) {
    float nv = sqrtf(fmaxf(g[2304 + tid], 0.f));
    nv = fmaxf(nv, 1e-12f);
    if (tid < 48) snq[tid] = nv;
    else snk[tid - 48] = nv;
  }
  __syncthreads();
  float tv = temp[0];
  for (int i = tid; i < 2304; i += 256) {
    int c = i / 48, d = i % 48;
    sG[i] = sG[i] * tv / (snq[c] * snk[d]);
  }
  __syncthreads();
  if (tid < 48) {
    float mx = -1e30f;
    for (int d = 0; d < 48; d++) mx = fmaxf(mx, sG[tid * 48 + d]);
    float s = 0.f;
    for (int d = 0; d < 48; d++) {
      float e = expf(sG[tid * 48 + d] - mx);
      sAt[tid * 48 + d] = e;
      s += e;
    }
    float inv = 1.f / s;
    for (int d = 0; d < 48; d++) sAt[tid * 48 + d] *= inv;
  }
  __syncthreads();
  for (int i = tid; i < 2304; i += 256) {
    int o = i / 48, d = i % 48;
    float a = 0.f;
#pragma unroll 8
    for (int c = 0; c < 48; c++) a = fmaf(po[o * 48 + c], sAt[c * 48 + d], a);
    M[(size_t)b * 2304 + i] = a;
  }
}

// ---------------------------------------------------------------------------
// Launch
// ---------------------------------------------------------------------------
extern "C" void kernel_launch(void* const* d_in, const int* in_sizes, int n_in,
                              void* d_out, int out_size) {
  (void)in_sizes; (void)n_in; (void)out_size;
  const float* x      = (const float*)d_in[0];
  const float* pe_w   = (const float*)d_in[1];
  const float* n1_w   = (const float*)d_in[2];
  const float* n1_b   = (const float*)d_in[3];
  const float* temp   = (const float*)d_in[4];
  const float* qkv_w  = (const float*)d_in[5];
  const float* qkv_dw = (const float*)d_in[6];
  const float* po_w   = (const float*)d_in[7];
  const float* n2_w   = (const float*)d_in[8];
  const float* n2_b   = (const float*)d_in[9];
  const float* pi_w   = (const float*)d_in[10];
  const float* ffn_dw = (const float*)d_in[11];
  const float* fo_w   = (const float*)d_in[12];
  float* out = (float*)d_out;

  float *patch, *first, *part, *gfin, *M;
  __half *qkv0, *qk, *gate;
  cudaGetSymbolAddress((void**)&patch, g_patch);
  cudaGetSymbolAddress((void**)&qkv0,  g_qkv0);
  cudaGetSymbolAddress((void**)&qk,    g_qk);
  cudaGetSymbolAddress((void**)&first, g_first);
  cudaGetSymbolAddress((void**)&gate,  g_gate);
  cudaGetSymbolAddress((void**)&part,  g_part);
  cudaGetSymbolAddress((void**)&gfin,  g_gfin);
  cudaGetSymbolAddress((void**)&M,     g_M);

  constexpr int SM_T48 = (48 * 132 + 48 * 52 + 352) * 4;          // 35.9 KB
  constexpr int SM_FO  = (64 * 132 + 64 * 52 + 352) * 4;          // 47.4 KB
  constexpr int SM_AV  = 48 * PXD * 2 + (48 * 132 + 48 * 52 + 48 * 12) * 4;
  constexpr int SM_PG  = (48 + 32) * PXD * 2 +
                         (48 * 36 + 32 * 12 + 2 * PXD + 96) * 4;

  cudaFuncSetAttribute(k_av, cudaFuncAttributeMaxDynamicSharedMemorySize,
                       SM_AV);
  cudaFuncSetAttribute(k_pigate, cudaFuncAttributeMaxDynamicSharedMemorySize,
                       SM_PG);

  int gpix = Bb * Np / 128;  // 4096 pixel-tiles

  // 1. patch embed
  k_pe<<<Bb * Hh, 128>>>(x, pe_w, patch);

  // 2. LN(patch) -> qkv 1x1 (48 -> 144), fp16 out
  k_tgemm<48, 48, 48, true, false, float, __half>
      <<<dim3(3, gpix), 192, SM_T48>>>(patch, Cc, 0, qkv_w, n1_w, n1_b,
                                       nullptr, 0, qkv0, C3, C3);

  // 3. depthwise on q,k only
  k_dw96<<<(Bb * 96 * Hh * (Ww / 8) + 255) / 256, 256>>>(qkv0, qkv_dw, qk);

  // 4-6. gram -> reduce -> softmax + fold po_w into M
  k_gram<<<Bb * NPART, 96>>>(qk, part);
  k_red<<<(Bb * GSLOTS + 255) / 256, 256>>>(part, gfin);
  k_att<<<Bb, 256>>>(gfin, temp, po_w, M);

  // 7. first = patch + M @ dw(v)   (dw fused into staging)
  k_av<<<gpix, 192, SM_AV>>>(qkv0, patch, M, qkv_dw, first);

  // 8. fused LN2 + pi + dw + gelu -> gate fp16
  k_pigate<<<gpix, 256, SM_PG>>>(first, n2_w, n2_b, pi_w, ffn_dw, gate);

  // 9. out = first + fo 1x1 (127 -> 48)
  k_tgemm<127, 64, 48, false, true, __half, float>
      <<<dim3(1, gpix), 192, SM_FO>>>(gate, HID, 0, fo_w, nullptr, nullptr,
                                      first, Cc, out, Cc, Cc);
}